// round 15
// baseline (speedup 1.0000x reference)
#include <cuda_runtime.h>
#include <cuda_fp16.h>
#include <math.h>
#include <stdint.h>

#define DIM   768
#define HEADS 12
#define HD    64
#define WIN   14
#define NTOK  196
#define NWIN  50
#define MROWS 9800
#define GROWS 8192
#define MLPH  3072
#define QKVN  2304
#define SCALE 0.125f

// -------------------- scratch (device globals; no allocation) ----------------
__device__ __half g_xin_h [MROWS * DIM];
__device__ __half g_qkv_h [MROWS * QKVN];
__device__ __half g_attn_h[MROWS * DIM];
__device__ float  g_xres  [GROWS * DIM];
__device__ __half g_h2_h  [GROWS * DIM];
__device__ __half g_hid_h [GROWS * MLPH];
__device__ __half g_qkvwT [QKVN * DIM];
__device__ __half g_projwT[DIM * DIM];
__device__ __half g_fc1wT [MLPH * DIM];
__device__ __half g_fc2wT [DIM * MLPH];

// -------------------- helpers ------------------------------------------------
__device__ __forceinline__ void cp16(void* dst, const void* src) {
    uint32_t d = (uint32_t)__cvta_generic_to_shared(dst);
    asm volatile("cp.async.cg.shared.global [%0], [%1], 16;\n" :: "r"(d), "l"(src));
}
#define CP_COMMIT()  asm volatile("cp.async.commit_group;\n")
#define CP_WAIT2()   asm volatile("cp.async.wait_group 2;\n")

__device__ __forceinline__ uint32_t packh2(float lo, float hi) {
    uint32_t r;
    asm("cvt.rn.f16x2.f32 %0, %1, %2;" : "=r"(r) : "f"(hi), "f"(lo));
    return r;
}

__device__ __forceinline__ void blockReduce2(float& s, float& ss) {
    #pragma unroll
    for (int o = 16; o; o >>= 1) {
        s  += __shfl_xor_sync(0xffffffffu, s,  o);
        ss += __shfl_xor_sync(0xffffffffu, ss, o);
    }
    __shared__ float ra[8], rb[8];
    int warp = threadIdx.x >> 5, lane = threadIdx.x & 31;
    if (lane == 0) { ra[warp] = s; rb[warp] = ss; }
    __syncthreads();
    if (threadIdx.x == 0) {
        float t1 = 0.f, t2 = 0.f;
        #pragma unroll
        for (int i = 0; i < 8; i++) { t1 += ra[i]; t2 += rb[i]; }
        ra[0] = t1; rb[0] = t2;
    }
    __syncthreads();
    s = ra[0]; ss = rb[0];
}

// -------------------- LN1 + window partition (half out) ----------------------
__global__ __launch_bounds__(256) void ln1_kernel(
    const float* __restrict__ x, const float* __restrict__ g,
    const float* __restrict__ b, __half* __restrict__ out)
{
    int t = blockIdx.x;
    int w  = t / NTOK, tk = t % NTOK;
    int img = w / 25, wy = (w % 25) / 5, wx = w % 5;
    int ty = tk / WIN, tx = tk % WIN;
    int y = wy * WIN + ty, xc = wx * WIN + tx;
    __half* orow = out + (size_t)t * DIM;
    int tid = threadIdx.x;
    if (y >= 64 || xc >= 64) {
        orow[tid] = __float2half(0.f);
        orow[tid + 256] = __float2half(0.f);
        orow[tid + 512] = __float2half(0.f);
        return;
    }
    const float* row = x + (((size_t)img * 64 + y) * 64 + xc) * DIM;
    float v0 = row[tid], v1 = row[tid + 256], v2 = row[tid + 512];
    float s = v0 + v1 + v2, ss = v0 * v0 + v1 * v1 + v2 * v2;
    blockReduce2(s, ss);
    float mean = s * (1.f / DIM);
    float var  = ss * (1.f / DIM) - mean * mean;
    float rstd = rsqrtf(var + 1e-6f);
    orow[tid]       = __float2half((v0 - mean) * rstd * g[tid]       + b[tid]);
    orow[tid + 256] = __float2half((v1 - mean) * rstd * g[tid + 256] + b[tid + 256]);
    orow[tid + 512] = __float2half((v2 - mean) * rstd * g[tid + 512] + b[tid + 512]);
}

__global__ __launch_bounds__(256) void ln2_kernel(
    const float* __restrict__ xin, const float* __restrict__ g,
    const float* __restrict__ b, __half* __restrict__ out)
{
    int t = blockIdx.x;
    const float* row = xin + (size_t)t * DIM;
    __half* orow = out + (size_t)t * DIM;
    int tid = threadIdx.x;
    float v0 = row[tid], v1 = row[tid + 256], v2 = row[tid + 512];
    float s = v0 + v1 + v2, ss = v0 * v0 + v1 * v1 + v2 * v2;
    blockReduce2(s, ss);
    float mean = s * (1.f / DIM);
    float var  = ss * (1.f / DIM) - mean * mean;
    float rstd = rsqrtf(var + 1e-6f);
    orow[tid]       = __float2half((v0 - mean) * rstd * g[tid]       + b[tid]);
    orow[tid + 256] = __float2half((v1 - mean) * rstd * g[tid + 256] + b[tid + 256]);
    orow[tid + 512] = __float2half((v2 - mean) * rstd * g[tid + 512] + b[tid + 512]);
}

// -------------------- weight transpose fp32 -> half --------------------------
__global__ __launch_bounds__(256) void transpose_h(
    const float* __restrict__ in, __half* __restrict__ out, int R, int C)
{
    __shared__ float t[32][33];
    int bx = blockIdx.x << 5, by = blockIdx.y << 5;
    int lx = threadIdx.x, ly = threadIdx.y;
    #pragma unroll
    for (int j = 0; j < 4; j++) {
        int r = by + ly + j * 8, c = bx + lx;
        if (r < R && c < C) t[ly + j * 8][lx] = in[(size_t)r * C + c];
    }
    __syncthreads();
    #pragma unroll
    for (int j = 0; j < 4; j++) {
        int oc = by + lx, orr = bx + ly + j * 8;
        if (orr < C && oc < R) out[(size_t)orr * R + oc] = __float2half(t[lx][ly + j * 8]);
    }
}

// -------------------- fp16 tensor-core GEMM ----------------------------------
// 128x128 CTA tile, 4 warps of 64x64 (2x2), mma.m16n8k16, k=32 tiles,
// 4-stage cp.async ring (R12 mainloop structure; fat warps cut ldsm traffic).
#define RSTR 80                     // bytes per smem row (32 halves + 16B pad)
#define ASTG (128 * RSTR)           // 10240 B per A stage
#define STG2 (2 * ASTG)             // A+B per stage
#define STAGES 4
#define GEMM_SMEM (STAGES * STG2)   // 81920 B

template<bool GATHER, bool GELU_ACT, bool RES, bool HALF_OUT>
__global__ __launch_bounds__(128, 2) void gemm_h(
    const __half* __restrict__ A, const __half* __restrict__ Bt,
    const float* __restrict__ bias, const float* __restrict__ Rs,
    void* __restrict__ Cv, int M, int Nn, int K)
{
    extern __shared__ char smc[];
    const int tid  = threadIdx.x;
    const int lane = tid & 31;
    const int warp = tid >> 5;
    const int wm = warp >> 1;       // 0..1 : 64-row slab
    const int wn = warp & 1;        // 0..1 : 64-col slab
    const int bm = blockIdx.y << 7;
    const int bn = blockIdx.x << 7;
    const int KT = K >> 5;

    // ---- load assignments: one 128-row, each thread owns one row (64B) ----
    const int lrow = tid;           // 0..127
    int gm = bm + lrow;
    int arow = gm < M ? gm : M - 1;
    if (GATHER) {
        int img = arow >> 12, rem = arow & 4095;
        int y = rem >> 6, xc = rem & 63;
        arow = (img * 25 + (y / WIN) * 5 + (xc / WIN)) * NTOK
             + (y % WIN) * WIN + (xc % WIN);
    }
    const __half* srcA = A  + (size_t)arow * K;
    const __half* srcB = Bt + (size_t)(bn + lrow) * K;
    char* dA = smc + lrow * RSTR;
    char* dB = dA + ASTG;

    auto issue = [&](int kt, int s) {
        char* a = dA + s * STG2;
        char* b = dB + s * STG2;
        const __half* sa = srcA + kt * 32;
        const __half* sb = srcB + kt * 32;
        cp16(a,      sa);      cp16(a + 16, sa + 8);
        cp16(a + 32, sa + 16); cp16(a + 48, sa + 24);
        cp16(b,      sb);      cp16(b + 16, sb + 8);
        cp16(b + 32, sb + 16); cp16(b + 48, sb + 24);
    };

    // ---- fragment addressing ----
    uint32_t base0 = (uint32_t)__cvta_generic_to_shared(smc);
    const int l16 = lane & 15;
    const int lh  = lane >> 4;
    const uint32_t aoff = (uint32_t)((wm * 64 + l16) * RSTR + lh * 16);
    const uint32_t boff = (uint32_t)(ASTG + (wn * 64 + l16) * RSTR + lh * 16);

    float acc[4][8][4];
    #pragma unroll
    for (int i = 0; i < 4; i++)
        #pragma unroll
        for (int j = 0; j < 8; j++)
            #pragma unroll
            for (int c = 0; c < 4; c++) acc[i][j][c] = 0.f;

    issue(0, 0); CP_COMMIT();
    issue(1, 1); CP_COMMIT();
    issue(2, 2); CP_COMMIT();

    for (int kt = 0; kt < KT; kt++) {
        CP_WAIT2();
        __syncthreads();
        {
            int nk = kt + 3;
            if (nk < KT) issue(nk, nk & 3);
            CP_COMMIT();
        }

        uint32_t sb = base0 + (uint32_t)((kt & 3) * STG2);
        #pragma unroll
        for (int kh = 0; kh < 2; kh++) {
            uint32_t kb = (uint32_t)(kh * 32);
            uint32_t a[4][4], bw[4][4];
            #pragma unroll
            for (int mt = 0; mt < 4; mt++) {
                uint32_t ad = sb + aoff + (uint32_t)(mt * 16 * RSTR) + kb;
                asm volatile("ldmatrix.sync.aligned.m8n8.x4.shared.b16 {%0,%1,%2,%3}, [%4];"
                    : "=r"(a[mt][0]), "=r"(a[mt][1]), "=r"(a[mt][2]), "=r"(a[mt][3])
                    : "r"(ad));
            }
            #pragma unroll
            for (int g = 0; g < 4; g++) {
                uint32_t bd = sb + boff + (uint32_t)(g * 16 * RSTR) + kb;
                asm volatile("ldmatrix.sync.aligned.m8n8.x4.shared.b16 {%0,%1,%2,%3}, [%4];"
                    : "=r"(bw[g][0]), "=r"(bw[g][1]), "=r"(bw[g][2]), "=r"(bw[g][3])
                    : "r"(bd));
            }
            #pragma unroll
            for (int mt = 0; mt < 4; mt++)
                #pragma unroll
                for (int nt = 0; nt < 8; nt++) {
                    int g = nt >> 1, t = nt & 1;
                    asm volatile(
                        "mma.sync.aligned.m16n8k16.row.col.f32.f16.f16.f32 "
                        "{%0,%1,%2,%3}, {%4,%5,%6,%7}, {%8,%9}, {%0,%1,%2,%3};"
                        : "+f"(acc[mt][nt][0]), "+f"(acc[mt][nt][1]),
                          "+f"(acc[mt][nt][2]), "+f"(acc[mt][nt][3])
                        : "r"(a[mt][0]), "r"(a[mt][1]), "r"(a[mt][2]), "r"(a[mt][3]),
                          "r"(bw[g][t]), "r"(bw[g][t + 2]));
                }
        }
    }

    // ---- epilogue ----
    const int rbase = bm + wm * 64 + (lane >> 2);
    const int cbase = bn + wn * 64 + (lane & 3) * 2;
    float* Cf = (float*)Cv;
    __half* Ch = (__half*)Cv;
    #pragma unroll
    for (int nt = 0; nt < 8; nt++) {
        int col = cbase + nt * 8;
        float bs0 = bias[col], bs1 = bias[col + 1];
        #pragma unroll
        for (int mt = 0; mt < 4; mt++) {
            int r0 = rbase + mt * 16;
            int r1 = r0 + 8;
            float v00 = acc[mt][nt][0] + bs0;
            float v01 = acc[mt][nt][1] + bs1;
            float v10 = acc[mt][nt][2] + bs0;
            float v11 = acc[mt][nt][3] + bs1;
            if (GELU_ACT) {
                v00 = 0.5f * v00 * (1.f + erff(v00 * 0.70710678f));
                v01 = 0.5f * v01 * (1.f + erff(v01 * 0.70710678f));
                v10 = 0.5f * v10 * (1.f + erff(v10 * 0.70710678f));
                v11 = 0.5f * v11 * (1.f + erff(v11 * 0.70710678f));
            }
            if (r0 < M) {
                if (RES) {
                    const float* rr = Rs + (size_t)r0 * Nn + col;
                    v00 += rr[0]; v01 += rr[1];
                }
                if (HALF_OUT)
                    *(uint32_t*)(Ch + (size_t)r0 * Nn + col) = packh2(v00, v01);
                else
                    *(float2*)(Cf + (size_t)r0 * Nn + col) = make_float2(v00, v01);
            }
            if (r1 < M) {
                if (RES) {
                    const float* rr = Rs + (size_t)r1 * Nn + col;
                    v10 += rr[0]; v11 += rr[1];
                }
                if (HALF_OUT)
                    *(uint32_t*)(Ch + (size_t)r1 * Nn + col) = packh2(v10, v11);
                else
                    *(float2*)(Cf + (size_t)r1 * Nn + col) = make_float2(v10, v11);
            }
        }
    }
}

// -------------------- mma attention: one CTA per (window, head) --------------
#define ATT_STR   144
#define ATT_Q     0
#define ATT_K     29952
#define ATT_V     59904
#define ATT_RH    89856
#define ATT_RW    101504
#define ATT_SMEM  113152

__global__ __launch_bounds__(256, 1) void attn_mma(
    const __half* __restrict__ qkv, const float* __restrict__ relh,
    const float* __restrict__ relw, __half* __restrict__ outp)
{
    extern __shared__ char smb[];
    uint32_t sbase = (uint32_t)__cvta_generic_to_shared(smb);
    float* rh = (float*)(smb + ATT_RH);
    float* rw = (float*)(smb + ATT_RW);

    const int blk = blockIdx.x;
    const int w = blk / HEADS, h = blk % HEADS;
    const int tid = threadIdx.x, lane = tid & 31, warp = tid >> 5;

    const __half* qbase = qkv + (size_t)w * NTOK * QKVN + h * HD;
    for (int idx = tid; idx < 196 * 8 * 3; idx += 256) {
        int mat = idx / (196 * 8);
        int rem = idx - mat * (196 * 8);
        int j = rem >> 3, c = rem & 7;
        const uint4* src = (const uint4*)(qbase + (size_t)j * QKVN + mat * DIM + c * 8);
        *(uint4*)(smb + mat * 29952 + j * ATT_STR + c * 16) = *src;
    }
    for (int idx = tid; idx < 12 * 9 * 3; idx += 256) {
        int mat = idx / (12 * 9);
        int rem = idx - mat * (12 * 9);
        int j = 196 + rem / 9, c = rem % 9;
        *(uint4*)(smb + mat * 29952 + j * ATT_STR + c * 16) = make_uint4(0, 0, 0, 0);
    }
    __syncthreads();

    for (int idx = tid; idx < 2 * 196 * 14; idx += 256) {
        int sel = idx / (196 * 14);
        int rem = idx - sel * (196 * 14);
        int i = rem / 14, k = rem - i * 14;
        int coord = (sel ? (i % 14) : (i / 14)) - k + 13;
        const float2* tab = (const float2*)((sel ? relw : relh) + coord * HD);
        const __half2* qrow = (const __half2*)(smb + ATT_Q + i * ATT_STR);
        float s = 0.f;
        #pragma unroll 8
        for (int d2 = 0; d2 < 32; d2++) {
            float2 qq = __half22float2(qrow[d2]);
            float2 tv = tab[d2];
            s += qq.x * tv.x + qq.y * tv.y;
        }
        (sel ? rw : rh)[i * 14 + k] = s;
    }
    for (int idx = tid; idx < 2 * 12 * 14; idx += 256) {
        int sel = idx / (12 * 14);
        int rem = idx - sel * (12 * 14);
        (sel ? rw : rh)[(196 + rem / 14) * 14 + rem % 14] = 0.f;
    }
    __syncthreads();

    const int g = lane >> 2, qt = lane & 3;
    const int l8 = lane & 7;
    const int sel8 = (lane >> 3) & 1;

    for (int mt = warp; mt < 13; mt += 8) {
        uint32_t qf[4][4];
        #pragma unroll
        for (int ks = 0; ks < 4; ks++) {
            uint32_t ad = sbase + ATT_Q + (uint32_t)((mt * 16 + (lane & 15)) * ATT_STR
                        + ks * 32 + (lane >> 4) * 16);
            asm volatile("ldmatrix.sync.aligned.m8n8.x4.shared.b16 {%0,%1,%2,%3}, [%4];"
                : "=r"(qf[ks][0]), "=r"(qf[ks][1]), "=r"(qf[ks][2]), "=r"(qf[ks][3])
                : "r"(ad));
        }

        float S[26][4];
        const int i0 = mt * 16 + g, i1 = i0 + 8;
        #pragma unroll
        for (int nt = 0; nt < 26; nt++) {
            float s0 = 0.f, s1 = 0.f, s2 = 0.f, s3 = 0.f;
            #pragma unroll
            for (int ks = 0; ks < 4; ks++) {
                uint32_t kd = sbase + ATT_K + (uint32_t)((nt * 8 + l8) * ATT_STR
                            + ks * 32 + sel8 * 16);
                uint32_t b0, b1;
                asm volatile("ldmatrix.sync.aligned.m8n8.x2.shared.b16 {%0,%1}, [%2];"
                    : "=r"(b0), "=r"(b1) : "r"(kd));
                asm volatile(
                    "mma.sync.aligned.m16n8k16.row.col.f32.f16.f16.f32 "
                    "{%0,%1,%2,%3}, {%4,%5,%6,%7}, {%8,%9}, {%0,%1,%2,%3};"
                    : "+f"(s0), "+f"(s1), "+f"(s2), "+f"(s3)
                    : "r"(qf[ks][0]), "r"(qf[ks][1]), "r"(qf[ks][2]), "r"(qf[ks][3]),
                      "r"(b0), "r"(b1));
            }
            int j0 = nt * 8 + 2 * qt, j1 = j0 + 1;
            int jh0 = (j0 * 4682) >> 16, jw0 = j0 - 14 * jh0;
            int jh1 = (j1 * 4682) >> 16, jw1 = j1 - 14 * jh1;
            S[nt][0] = (j0 < 196) ? s0 * SCALE + rh[i0 * 14 + jh0] + rw[i0 * 14 + jw0] : -1e30f;
            S[nt][1] = (j1 < 196) ? s1 * SCALE + rh[i0 * 14 + jh1] + rw[i0 * 14 + jw1] : -1e30f;
            S[nt][2] = (j0 < 196) ? s2 * SCALE + rh[i1 * 14 + jh0] + rw[i1 * 14 + jw0] : -1e30f;
            S[nt][3] = (j1 < 196) ? s3 * SCALE + rh[i1 * 14 + jh1] + rw[i1 * 14 + jw1] : -1e30f;
        }

        float mx0 = -1e30f, mx1 = -1e30f;
        #pragma unroll
        for (int nt = 0; nt < 26; nt++) {
            mx0 = fmaxf(mx0, fmaxf(S[nt][0], S[nt][1]));
            mx1 = fmaxf(mx1, fmaxf(S[nt][2], S[nt][3]));
        }
        mx0 = fmaxf(mx0, __shfl_xor_sync(0xffffffffu, mx0, 1));
        mx0 = fmaxf(mx0, __shfl_xor_sync(0xffffffffu, mx0, 2));
        mx1 = fmaxf(mx1, __shfl_xor_sync(0xffffffffu, mx1, 1));
        mx1 = fmaxf(mx1, __shfl_xor_sync(0xffffffffu, mx1, 2));
        float sum0 = 0.f, sum1 = 0.f;
        #pragma unroll
        for (int nt = 0; nt < 26; nt++) {
            S[nt][0] = __expf(S[nt][0] - mx0); sum0 += S[nt][0];
            S[nt][1] = __expf(S[nt][1] - mx0); sum0 += S[nt][1];
            S[nt][2] = __expf(S[nt][2] - mx1); sum1 += S[nt][2];
            S[nt][3] = __expf(S[nt][3] - mx1); sum1 += S[nt][3];
        }
        sum0 += __shfl_xor_sync(0xffffffffu, sum0, 1);
        sum0 += __shfl_xor_sync(0xffffffffu, sum0, 2);
        sum1 += __shfl_xor_sync(0xffffffffu, sum1, 1);
        sum1 += __shfl_xor_sync(0xffffffffu, sum1, 2);

        float O[8][4];
        #pragma unroll
        for (int nt = 0; nt < 8; nt++)
            #pragma unroll
            for (int c = 0; c < 4; c++) O[nt][c] = 0.f;

        #pragma unroll
        for (int kc = 0; kc < 13; kc++) {
            uint32_t p0 = packh2(S[2*kc][0],   S[2*kc][1]);
            uint32_t p1 = packh2(S[2*kc][2],   S[2*kc][3]);
            uint32_t p2 = packh2(S[2*kc+1][0], S[2*kc+1][1]);
            uint32_t p3 = packh2(S[2*kc+1][2], S[2*kc+1][3]);
            #pragma unroll
            for (int nt = 0; nt < 8; nt++) {
                uint32_t vd = sbase + ATT_V + (uint32_t)((kc * 16 + sel8 * 8 + l8) * ATT_STR
                            + nt * 16);
                uint32_t v0, v1;
                asm volatile("ldmatrix.sync.aligned.m8n8.x2.trans.shared.b16 {%0,%1}, [%2];"
                    : "=r"(v0), "=r"(v1) : "r"(vd));
                asm volatile(
                    "mma.sync.aligned.m16n8k16.row.col.f32.f16.f16.f32 "
                    "{%0,%1,%2,%3}, {%4,%5,%6,%7}, {%8,%9}, {%0,%1,%2,%3};"
                    : "+f"(O[nt][0]), "+f"(O[nt][1]), "+f"(O[nt][2]), "+f"(O[nt][3])
                    : "r"(p0), "r"(p1), "r"(p2), "r"(p3), "r"(v0), "r"(v1));
            }
        }

        float inv0 = 1.f / sum0, inv1 = 1.f / sum1;
        if (i0 < 196) {
            __half* orow = outp + ((size_t)w * NTOK + i0) * DIM + h * HD;
            #pragma unroll
            for (int nt = 0; nt < 8; nt++)
                *(uint32_t*)(orow + nt * 8 + 2 * qt) =
                    packh2(O[nt][0] * inv0, O[nt][1] * inv0);
        }
        if (i1 < 196) {
            __half* orow = outp + ((size_t)w * NTOK + i1) * DIM + h * HD;
            #pragma unroll
            for (int nt = 0; nt < 8; nt++)
                *(uint32_t*)(orow + nt * 8 + 2 * qt) =
                    packh2(O[nt][2] * inv1, O[nt][3] * inv1);
        }
    }
}

// -------------------- launch -------------------------------------------------
extern "C" void kernel_launch(void* const* d_in, const int* in_sizes, int n_in,
                              void* d_out, int out_size)
{
    const float* x      = (const float*)d_in[0];
    const float* ln1_g  = (const float*)d_in[1];
    const float* ln1_b  = (const float*)d_in[2];
    const float* qkv_w  = (const float*)d_in[3];
    const float* qkv_b  = (const float*)d_in[4];
    const float* proj_w = (const float*)d_in[5];
    const float* proj_b = (const float*)d_in[6];
    const float* rel_h  = (const float*)d_in[7];
    const float* rel_w  = (const float*)d_in[8];
    const float* ln2_g  = (const float*)d_in[9];
    const float* ln2_b  = (const float*)d_in[10];
    const float* fc1_w  = (const float*)d_in[11];
    const float* fc1_b  = (const float*)d_in[12];
    const float* fc2_w  = (const float*)d_in[13];
    const float* fc2_b  = (const float*)d_in[14];
    float* out = (float*)d_out;

    __half *p_xin, *p_qkv, *p_attn, *p_h2, *p_hid;
    __half *p_qkvT, *p_projT, *p_fc1T, *p_fc2T;
    float *p_xres;
    cudaGetSymbolAddress((void**)&p_xin,  g_xin_h);
    cudaGetSymbolAddress((void**)&p_qkv,  g_qkv_h);
    cudaGetSymbolAddress((void**)&p_attn, g_attn_h);
    cudaGetSymbolAddress((void**)&p_xres, g_xres);
    cudaGetSymbolAddress((void**)&p_h2,   g_h2_h);
    cudaGetSymbolAddress((void**)&p_hid,  g_hid_h);
    cudaGetSymbolAddress((void**)&p_qkvT,  g_qkvwT);
    cudaGetSymbolAddress((void**)&p_projT, g_projwT);
    cudaGetSymbolAddress((void**)&p_fc1T,  g_fc1wT);
    cudaGetSymbolAddress((void**)&p_fc2T,  g_fc2wT);

    cudaFuncSetAttribute(attn_mma, cudaFuncAttributeMaxDynamicSharedMemorySize, ATT_SMEM);
    cudaFuncSetAttribute((const void*)gemm_h<false, false, false, true>,
                         cudaFuncAttributeMaxDynamicSharedMemorySize, GEMM_SMEM);
    cudaFuncSetAttribute((const void*)gemm_h<true, false, true, false>,
                         cudaFuncAttributeMaxDynamicSharedMemorySize, GEMM_SMEM);
    cudaFuncSetAttribute((const void*)gemm_h<false, true, false, true>,
                         cudaFuncAttributeMaxDynamicSharedMemorySize, GEMM_SMEM);
    cudaFuncSetAttribute((const void*)gemm_h<false, false, true, false>,
                         cudaFuncAttributeMaxDynamicSharedMemorySize, GEMM_SMEM);

    dim3 tb(32, 8);
    transpose_h<<<dim3(QKVN / 32, DIM / 32), tb>>>(qkv_w,  p_qkvT,  DIM, QKVN);
    transpose_h<<<dim3(DIM / 32,  DIM / 32), tb>>>(proj_w, p_projT, DIM, DIM);
    transpose_h<<<dim3(MLPH / 32, DIM / 32), tb>>>(fc1_w,  p_fc1T,  DIM, MLPH);
    transpose_h<<<dim3(DIM / 32,  MLPH / 32), tb>>>(fc2_w, p_fc2T,  MLPH, DIM);

    // 1. LN1 + window partition (half out)
    ln1_kernel<<<MROWS, 256>>>(x, ln1_g, ln1_b, p_xin);

    // 2. QKV GEMM -> half
    gemm_h<false, false, false, true><<<dim3(QKVN / 128, (MROWS + 127) / 128), 128, GEMM_SMEM>>>(
        p_xin, p_qkvT, qkv_b, nullptr, p_qkv, MROWS, QKVN, DIM);

    // 3. mma attention (half out)
    attn_mma<<<NWIN * HEADS, 256, ATT_SMEM>>>(p_qkv, rel_h, rel_w, p_attn);

    // 4. proj GEMM + gather + residual -> fp32 xres
    gemm_h<true, false, true, false><<<dim3(DIM / 128, GROWS / 128), 128, GEMM_SMEM>>>(
        p_attn, p_projT, proj_b, x, p_xres, GROWS, DIM, DIM);

    // 5. LN2 (half out)
    ln2_kernel<<<GROWS, 256>>>(p_xres, ln2_g, ln2_b, p_h2);

    // 6. fc1 + GELU (half out)
    gemm_h<false, true, false, true><<<dim3(MLPH / 128, GROWS / 128), 128, GEMM_SMEM>>>(
        p_h2, p_fc1T, fc1_b, nullptr, p_hid, GROWS, MLPH, DIM);

    // 7. fc2 + residual -> out (fp32)
    gemm_h<false, false, true, false><<<dim3(DIM / 128, GROWS / 128), 128, GEMM_SMEM>>>(
        p_hid, p_fc2T, fc2_b, p_xres, out, GROWS, DIM, MLPH);
}

// round 16
// speedup vs baseline: 1.2375x; 1.2375x over previous
#include <cuda_runtime.h>
#include <cuda_fp16.h>
#include <math.h>
#include <stdint.h>

#define DIM   768
#define HEADS 12
#define HD    64
#define WIN   14
#define NTOK  196
#define NWIN  50
#define GROWS 8192
#define MLPH  3072
#define QKVN  2304
#define SCALE 0.125f

// -------------------- scratch (device globals; no allocation) ----------------
__device__ __half g_xin_h [GROWS * DIM];    // LN1 out (half), token layout
__device__ __half g_qkv_h [GROWS * QKVN];   // qkv (half), token layout
__device__ __half g_attn_h[GROWS * DIM];    // attention out (half), token layout
__device__ float  g_xres  [GROWS * DIM];    // x + proj (fp32 master)
__device__ __half g_h2_h  [GROWS * DIM];    // LN2 out (half)
__device__ __half g_hid_h [GROWS * MLPH];   // gelu(fc1) (half)
__device__ __half g_qkvwT [QKVN * DIM];
__device__ __half g_projwT[DIM * DIM];
__device__ __half g_fc1wT [MLPH * DIM];
__device__ __half g_fc2wT [DIM * MLPH];
__device__ __half g_qkvb_h[QKVN];           // qkv bias (half) for padded tokens

// -------------------- helpers ------------------------------------------------
__device__ __forceinline__ void cp16(void* dst, const void* src) {
    uint32_t d = (uint32_t)__cvta_generic_to_shared(dst);
    asm volatile("cp.async.cg.shared.global [%0], [%1], 16;\n" :: "r"(d), "l"(src));
}
#define CP_COMMIT()  asm volatile("cp.async.commit_group;\n")
#define CP_WAIT2()   asm volatile("cp.async.wait_group 2;\n")

__device__ __forceinline__ uint32_t packh2(float lo, float hi) {
    uint32_t r;
    asm("cvt.rn.f16x2.f32 %0, %1, %2;" : "=r"(r) : "f"(hi), "f"(lo));
    return r;
}

__device__ __forceinline__ void blockReduce2(float& s, float& ss) {
    #pragma unroll
    for (int o = 16; o; o >>= 1) {
        s  += __shfl_xor_sync(0xffffffffu, s,  o);
        ss += __shfl_xor_sync(0xffffffffu, ss, o);
    }
    __shared__ float ra[8], rb[8];
    int warp = threadIdx.x >> 5, lane = threadIdx.x & 31;
    if (lane == 0) { ra[warp] = s; rb[warp] = ss; }
    __syncthreads();
    if (threadIdx.x == 0) {
        float t1 = 0.f, t2 = 0.f;
        #pragma unroll
        for (int i = 0; i < 8; i++) { t1 += ra[i]; t2 += rb[i]; }
        ra[0] = t1; rb[0] = t2;
    }
    __syncthreads();
    s = ra[0]; ss = rb[0];
}

// -------------------- LayerNorm (token rows, half out) -----------------------
__global__ __launch_bounds__(256) void ln_kernel(
    const float* __restrict__ xin, const float* __restrict__ g,
    const float* __restrict__ b, __half* __restrict__ out)
{
    int t = blockIdx.x;
    const float* row = xin + (size_t)t * DIM;
    __half* orow = out + (size_t)t * DIM;
    int tid = threadIdx.x;
    float v0 = row[tid], v1 = row[tid + 256], v2 = row[tid + 512];
    float s = v0 + v1 + v2, ss = v0 * v0 + v1 * v1 + v2 * v2;
    blockReduce2(s, ss);
    float mean = s * (1.f / DIM);
    float var  = ss * (1.f / DIM) - mean * mean;
    float rstd = rsqrtf(var + 1e-6f);
    orow[tid]       = __float2half((v0 - mean) * rstd * g[tid]       + b[tid]);
    orow[tid + 256] = __float2half((v1 - mean) * rstd * g[tid + 256] + b[tid + 256]);
    orow[tid + 512] = __float2half((v2 - mean) * rstd * g[tid + 512] + b[tid + 512]);
}

// -------------------- all weight transposes + bias, one launch ---------------
// tiles: qkv 72x24 | proj 24x24 | fc1 96x24 | fc2 24x96 ; last block = bias
#define T_QKV  1728
#define T_PROJ (T_QKV + 576)
#define T_FC1  (T_PROJ + 2304)
#define T_FC2  (T_FC1 + 2304)
#define T_ALL  (T_FC2 + 1)

__global__ __launch_bounds__(256) void transpose_all(
    const float* __restrict__ qkv_w,  __half* __restrict__ qkvT,
    const float* __restrict__ proj_w, __half* __restrict__ projT,
    const float* __restrict__ fc1_w,  __half* __restrict__ fc1T,
    const float* __restrict__ fc2_w,  __half* __restrict__ fc2T,
    const float* __restrict__ qkv_b,  __half* __restrict__ qkvb)
{
    int t = blockIdx.x;
    int lx = threadIdx.x & 31, ly = threadIdx.x >> 5;
    if (t >= T_FC2) {
        // bias convert: 2304 halves
        for (int i = threadIdx.x; i < QKVN; i += 256)
            qkvb[i] = __float2half(qkv_b[i]);
        return;
    }
    const float* in; __half* out; int R, C, nx;
    if (t < T_QKV)       { in = qkv_w;  out = qkvT;  R = DIM;  C = QKVN; nx = 72; }
    else if (t < T_PROJ) { t -= T_QKV;  in = proj_w; out = projT; R = DIM;  C = DIM;  nx = 24; }
    else if (t < T_FC1)  { t -= T_PROJ; in = fc1_w;  out = fc1T;  R = DIM;  C = MLPH; nx = 96; }
    else                 { t -= T_FC1;  in = fc2_w;  out = fc2T;  R = MLPH; C = DIM;  nx = 24; }
    int bx = (t % nx) << 5, by = (t / nx) << 5;

    __shared__ float tl[32][33];
    #pragma unroll
    for (int j = 0; j < 4; j++) {
        int r = by + ly + j * 8, c = bx + lx;
        tl[ly + j * 8][lx] = in[(size_t)r * C + c];
    }
    __syncthreads();
    #pragma unroll
    for (int j = 0; j < 4; j++) {
        int oc = by + lx, orr = bx + ly + j * 8;
        out[(size_t)orr * R + oc] = __float2half(tl[lx][ly + j * 8]);
    }
}

// -------------------- fp16 tensor-core GEMM (R12 config) ---------------------
// 128x128 CTA tile, 8 warps (64x32), mma.m16n8k16, k=32 tiles, 4-stage cp.async
#define RSTR 80
#define ASTG (128 * RSTR)
#define STG2 (2 * ASTG)
#define STAGES 4
#define GEMM_SMEM (STAGES * STG2)

template<bool GELU_ACT, bool RES, bool HALF_OUT>
__global__ __launch_bounds__(256, 2) void gemm_h(
    const __half* __restrict__ A, const __half* __restrict__ Bt,
    const float* __restrict__ bias, const float* __restrict__ Rs,
    void* __restrict__ Cv, int M, int Nn, int K)
{
    extern __shared__ char smc[];
    const int tid  = threadIdx.x;
    const int lane = tid & 31;
    const int warp = tid >> 5;
    const int wm = warp >> 2;
    const int wn = warp & 3;
    const int bm = blockIdx.y << 7;
    const int bn = blockIdx.x << 7;
    const int KT = K >> 5;

    const int lrow = tid >> 1;
    const int lch  = tid & 1;
    int gm = bm + lrow;
    int arow = gm < M ? gm : M - 1;
    const __half* srcA = A  + (size_t)arow * K + lch * 16;
    const __half* srcB = Bt + (size_t)(bn + lrow) * K + lch * 16;
    char* dA = smc + lrow * RSTR + lch * 32;
    char* dB = dA + ASTG;

    auto issue = [&](int kt, int s) {
        char* a = dA + s * STG2;
        char* b = dB + s * STG2;
        const __half* sa = srcA + kt * 32;
        const __half* sb = srcB + kt * 32;
        cp16(a, sa); cp16(a + 16, sa + 8);
        cp16(b, sb); cp16(b + 16, sb + 8);
    };

    uint32_t base0 = (uint32_t)__cvta_generic_to_shared(smc);
    const int l16 = lane & 15;
    const int lh  = lane >> 4;
    const uint32_t aoff = (uint32_t)((wm * 64 + l16) * RSTR + lh * 16);
    const uint32_t boff = (uint32_t)(ASTG + (wn * 32 + l16) * RSTR + lh * 16);

    float acc[4][4][4];
    #pragma unroll
    for (int i = 0; i < 4; i++)
        #pragma unroll
        for (int j = 0; j < 4; j++)
            #pragma unroll
            for (int c = 0; c < 4; c++) acc[i][j][c] = 0.f;

    issue(0, 0); CP_COMMIT();
    issue(1, 1); CP_COMMIT();
    issue(2, 2); CP_COMMIT();

    for (int kt = 0; kt < KT; kt++) {
        CP_WAIT2();
        __syncthreads();
        {
            int nk = kt + 3;
            if (nk < KT) issue(nk, nk & 3);
            CP_COMMIT();
        }

        uint32_t sb = base0 + (uint32_t)((kt & 3) * STG2);
        #pragma unroll
        for (int kh = 0; kh < 2; kh++) {
            uint32_t kb = (uint32_t)(kh * 32);
            uint32_t a[4][4], bw[2][4];
            #pragma unroll
            for (int mt = 0; mt < 4; mt++) {
                uint32_t ad = sb + aoff + (uint32_t)(mt * 16 * RSTR) + kb;
                asm volatile("ldmatrix.sync.aligned.m8n8.x4.shared.b16 {%0,%1,%2,%3}, [%4];"
                    : "=r"(a[mt][0]), "=r"(a[mt][1]), "=r"(a[mt][2]), "=r"(a[mt][3])
                    : "r"(ad));
            }
            #pragma unroll
            for (int g = 0; g < 2; g++) {
                uint32_t bd = sb + boff + (uint32_t)(g * 16 * RSTR) + kb;
                asm volatile("ldmatrix.sync.aligned.m8n8.x4.shared.b16 {%0,%1,%2,%3}, [%4];"
                    : "=r"(bw[g][0]), "=r"(bw[g][1]), "=r"(bw[g][2]), "=r"(bw[g][3])
                    : "r"(bd));
            }
            #pragma unroll
            for (int mt = 0; mt < 4; mt++)
                #pragma unroll
                for (int nt = 0; nt < 4; nt++) {
                    int g = nt >> 1, t = nt & 1;
                    asm volatile(
                        "mma.sync.aligned.m16n8k16.row.col.f32.f16.f16.f32 "
                        "{%0,%1,%2,%3}, {%4,%5,%6,%7}, {%8,%9}, {%0,%1,%2,%3};"
                        : "+f"(acc[mt][nt][0]), "+f"(acc[mt][nt][1]),
                          "+f"(acc[mt][nt][2]), "+f"(acc[mt][nt][3])
                        : "r"(a[mt][0]), "r"(a[mt][1]), "r"(a[mt][2]), "r"(a[mt][3]),
                          "r"(bw[g][t]), "r"(bw[g][t + 2]));
                }
        }
    }

    const int rbase = bm + wm * 64 + (lane >> 2);
    const int cbase = bn + wn * 32 + (lane & 3) * 2;
    float* Cf = (float*)Cv;
    __half* Ch = (__half*)Cv;
    #pragma unroll
    for (int nt = 0; nt < 4; nt++) {
        int col = cbase + nt * 8;
        float bs0 = bias[col], bs1 = bias[col + 1];
        #pragma unroll
        for (int mt = 0; mt < 4; mt++) {
            int r0 = rbase + mt * 16;
            int r1 = r0 + 8;
            float v00 = acc[mt][nt][0] + bs0;
            float v01 = acc[mt][nt][1] + bs1;
            float v10 = acc[mt][nt][2] + bs0;
            float v11 = acc[mt][nt][3] + bs1;
            if (GELU_ACT) {
                v00 = 0.5f * v00 * (1.f + erff(v00 * 0.70710678f));
                v01 = 0.5f * v01 * (1.f + erff(v01 * 0.70710678f));
                v10 = 0.5f * v10 * (1.f + erff(v10 * 0.70710678f));
                v11 = 0.5f * v11 * (1.f + erff(v11 * 0.70710678f));
            }
            if (r0 < M) {
                if (RES) {
                    const float* rr = Rs + (size_t)r0 * Nn + col;
                    v00 += rr[0]; v01 += rr[1];
                }
                if (HALF_OUT)
                    *(uint32_t*)(Ch + (size_t)r0 * Nn + col) = packh2(v00, v01);
                else
                    *(float2*)(Cf + (size_t)r0 * Nn + col) = make_float2(v00, v01);
            }
            if (r1 < M) {
                if (RES) {
                    const float* rr = Rs + (size_t)r1 * Nn + col;
                    v10 += rr[0]; v11 += rr[1];
                }
                if (HALF_OUT)
                    *(uint32_t*)(Ch + (size_t)r1 * Nn + col) = packh2(v10, v11);
                else
                    *(float2*)(Cf + (size_t)r1 * Nn + col) = make_float2(v10, v11);
            }
        }
    }
}

// -------------------- mma attention: one CTA per (window, head) --------------
// gathers QKV rows from token layout; padded tokens use qkv bias.
#define ATT_STR   144
#define ATT_Q     0
#define ATT_K     29952
#define ATT_V     59904
#define ATT_RH    89856
#define ATT_RW    101504
#define ATT_SMEM  113152

__global__ __launch_bounds__(256, 1) void attn_mma(
    const __half* __restrict__ qkv, const __half* __restrict__ qkvb,
    const float* __restrict__ relh, const float* __restrict__ relw,
    __half* __restrict__ outp)
{
    extern __shared__ char smb[];
    uint32_t sbase = (uint32_t)__cvta_generic_to_shared(smb);
    float* rh = (float*)(smb + ATT_RH);
    float* rw = (float*)(smb + ATT_RW);

    const int blk = blockIdx.x;
    const int w = blk / HEADS, h = blk % HEADS;
    const int img = w / 25, wy = (w % 25) / 5, wx = w % 5;
    const int tid = threadIdx.x, lane = tid & 31, warp = tid >> 5;

    // ---- gather Q/K/V into smem (padded tokens -> qkv bias) ----
    for (int idx = tid; idx < 196 * 8 * 3; idx += 256) {
        int mat = idx / (196 * 8);
        int rem = idx - mat * (196 * 8);
        int j = rem >> 3, c = rem & 7;
        int ty = j / WIN, tx = j - ty * WIN;
        int y = wy * WIN + ty, xg = wx * WIN + tx;
        const uint4* src;
        if (y < 64 && xg < 64) {
            int row = img * 4096 + y * 64 + xg;
            src = (const uint4*)(qkv + (size_t)row * QKVN + mat * DIM + h * HD + c * 8);
        } else {
            src = (const uint4*)(qkvb + mat * DIM + h * HD + c * 8);
        }
        *(uint4*)(smb + mat * 29952 + j * ATT_STR + c * 16) = *src;
    }
    for (int idx = tid; idx < 12 * 9 * 3; idx += 256) {
        int mat = idx / (12 * 9);
        int rem = idx - mat * (12 * 9);
        int j = 196 + rem / 9, c = rem % 9;
        *(uint4*)(smb + mat * 29952 + j * ATT_STR + c * 16) = make_uint4(0, 0, 0, 0);
    }
    __syncthreads();

    // ---- rel tables ----
    for (int idx = tid; idx < 2 * 196 * 14; idx += 256) {
        int sel = idx / (196 * 14);
        int rem = idx - sel * (196 * 14);
        int i = rem / 14, k = rem - i * 14;
        int coord = (sel ? (i % 14) : (i / 14)) - k + 13;
        const float2* tab = (const float2*)((sel ? relw : relh) + coord * HD);
        const __half2* qrow = (const __half2*)(smb + ATT_Q + i * ATT_STR);
        float s = 0.f;
        #pragma unroll 8
        for (int d2 = 0; d2 < 32; d2++) {
            float2 qq = __half22float2(qrow[d2]);
            float2 tv = tab[d2];
            s += qq.x * tv.x + qq.y * tv.y;
        }
        (sel ? rw : rh)[i * 14 + k] = s;
    }
    for (int idx = tid; idx < 2 * 12 * 14; idx += 256) {
        int sel = idx / (12 * 14);
        int rem = idx - sel * (12 * 14);
        (sel ? rw : rh)[(196 + rem / 14) * 14 + rem % 14] = 0.f;
    }
    __syncthreads();

    const int g = lane >> 2, qt = lane & 3;
    const int l8 = lane & 7;
    const int sel8 = (lane >> 3) & 1;

    for (int mt = warp; mt < 13; mt += 8) {
        uint32_t qf[4][4];
        #pragma unroll
        for (int ks = 0; ks < 4; ks++) {
            uint32_t ad = sbase + ATT_Q + (uint32_t)((mt * 16 + (lane & 15)) * ATT_STR
                        + ks * 32 + (lane >> 4) * 16);
            asm volatile("ldmatrix.sync.aligned.m8n8.x4.shared.b16 {%0,%1,%2,%3}, [%4];"
                : "=r"(qf[ks][0]), "=r"(qf[ks][1]), "=r"(qf[ks][2]), "=r"(qf[ks][3])
                : "r"(ad));
        }

        float S[26][4];
        const int i0 = mt * 16 + g, i1 = i0 + 8;
        #pragma unroll
        for (int nt = 0; nt < 26; nt++) {
            float s0 = 0.f, s1 = 0.f, s2 = 0.f, s3 = 0.f;
            #pragma unroll
            for (int ks = 0; ks < 4; ks++) {
                uint32_t kd = sbase + ATT_K + (uint32_t)((nt * 8 + l8) * ATT_STR
                            + ks * 32 + sel8 * 16);
                uint32_t b0, b1;
                asm volatile("ldmatrix.sync.aligned.m8n8.x2.shared.b16 {%0,%1}, [%2];"
                    : "=r"(b0), "=r"(b1) : "r"(kd));
                asm volatile(
                    "mma.sync.aligned.m16n8k16.row.col.f32.f16.f16.f32 "
                    "{%0,%1,%2,%3}, {%4,%5,%6,%7}, {%8,%9}, {%0,%1,%2,%3};"
                    : "+f"(s0), "+f"(s1), "+f"(s2), "+f"(s3)
                    : "r"(qf[ks][0]), "r"(qf[ks][1]), "r"(qf[ks][2]), "r"(qf[ks][3]),
                      "r"(b0), "r"(b1));
            }
            int j0 = nt * 8 + 2 * qt, j1 = j0 + 1;
            int jh0 = (j0 * 4682) >> 16, jw0 = j0 - 14 * jh0;
            int jh1 = (j1 * 4682) >> 16, jw1 = j1 - 14 * jh1;
            S[nt][0] = (j0 < 196) ? s0 * SCALE + rh[i0 * 14 + jh0] + rw[i0 * 14 + jw0] : -1e30f;
            S[nt][1] = (j1 < 196) ? s1 * SCALE + rh[i0 * 14 + jh1] + rw[i0 * 14 + jw1] : -1e30f;
            S[nt][2] = (j0 < 196) ? s2 * SCALE + rh[i1 * 14 + jh0] + rw[i1 * 14 + jw0] : -1e30f;
            S[nt][3] = (j1 < 196) ? s3 * SCALE + rh[i1 * 14 + jh1] + rw[i1 * 14 + jw1] : -1e30f;
        }

        float mx0 = -1e30f, mx1 = -1e30f;
        #pragma unroll
        for (int nt = 0; nt < 26; nt++) {
            mx0 = fmaxf(mx0, fmaxf(S[nt][0], S[nt][1]));
            mx1 = fmaxf(mx1, fmaxf(S[nt][2], S[nt][3]));
        }
        mx0 = fmaxf(mx0, __shfl_xor_sync(0xffffffffu, mx0, 1));
        mx0 = fmaxf(mx0, __shfl_xor_sync(0xffffffffu, mx0, 2));
        mx1 = fmaxf(mx1, __shfl_xor_sync(0xffffffffu, mx1, 1));
        mx1 = fmaxf(mx1, __shfl_xor_sync(0xffffffffu, mx1, 2));
        float sum0 = 0.f, sum1 = 0.f;
        #pragma unroll
        for (int nt = 0; nt < 26; nt++) {
            S[nt][0] = __expf(S[nt][0] - mx0); sum0 += S[nt][0];
            S[nt][1] = __expf(S[nt][1] - mx0); sum0 += S[nt][1];
            S[nt][2] = __expf(S[nt][2] - mx1); sum1 += S[nt][2];
            S[nt][3] = __expf(S[nt][3] - mx1); sum1 += S[nt][3];
        }
        sum0 += __shfl_xor_sync(0xffffffffu, sum0, 1);
        sum0 += __shfl_xor_sync(0xffffffffu, sum0, 2);
        sum1 += __shfl_xor_sync(0xffffffffu, sum1, 1);
        sum1 += __shfl_xor_sync(0xffffffffu, sum1, 2);

        float O[8][4];
        #pragma unroll
        for (int nt = 0; nt < 8; nt++)
            #pragma unroll
            for (int c = 0; c < 4; c++) O[nt][c] = 0.f;

        #pragma unroll
        for (int kc = 0; kc < 13; kc++) {
            uint32_t p0 = packh2(S[2*kc][0],   S[2*kc][1]);
            uint32_t p1 = packh2(S[2*kc][2],   S[2*kc][3]);
            uint32_t p2 = packh2(S[2*kc+1][0], S[2*kc+1][1]);
            uint32_t p3 = packh2(S[2*kc+1][2], S[2*kc+1][3]);
            #pragma unroll
            for (int nt = 0; nt < 8; nt++) {
                uint32_t vd = sbase + ATT_V + (uint32_t)((kc * 16 + sel8 * 8 + l8) * ATT_STR
                            + nt * 16);
                uint32_t v0, v1;
                asm volatile("ldmatrix.sync.aligned.m8n8.x2.trans.shared.b16 {%0,%1}, [%2];"
                    : "=r"(v0), "=r"(v1) : "r"(vd));
                asm volatile(
                    "mma.sync.aligned.m16n8k16.row.col.f32.f16.f16.f32 "
                    "{%0,%1,%2,%3}, {%4,%5,%6,%7}, {%8,%9}, {%0,%1,%2,%3};"
                    : "+f"(O[nt][0]), "+f"(O[nt][1]), "+f"(O[nt][2]), "+f"(O[nt][3])
                    : "r"(p0), "r"(p1), "r"(p2), "r"(p3), "r"(v0), "r"(v1));
            }
        }

        // ---- write out (token layout; skip padded tokens) ----
        float inv0 = 1.f / sum0, inv1 = 1.f / sum1;
        if (i0 < 196) {
            int ty = i0 / WIN, tx = i0 - ty * WIN;
            int y = wy * WIN + ty, xg = wx * WIN + tx;
            if (y < 64 && xg < 64) {
                __half* orow = outp + ((size_t)(img * 4096 + y * 64 + xg)) * DIM + h * HD;
                #pragma unroll
                for (int nt = 0; nt < 8; nt++)
                    *(uint32_t*)(orow + nt * 8 + 2 * qt) =
                        packh2(O[nt][0] * inv0, O[nt][1] * inv0);
            }
        }
        if (i1 < 196) {
            int ty = i1 / WIN, tx = i1 - ty * WIN;
            int y = wy * WIN + ty, xg = wx * WIN + tx;
            if (y < 64 && xg < 64) {
                __half* orow = outp + ((size_t)(img * 4096 + y * 64 + xg)) * DIM + h * HD;
                #pragma unroll
                for (int nt = 0; nt < 8; nt++)
                    *(uint32_t*)(orow + nt * 8 + 2 * qt) =
                        packh2(O[nt][2] * inv1, O[nt][3] * inv1);
            }
        }
    }
}

// -------------------- launch -------------------------------------------------
extern "C" void kernel_launch(void* const* d_in, const int* in_sizes, int n_in,
                              void* d_out, int out_size)
{
    const float* x      = (const float*)d_in[0];
    const float* ln1_g  = (const float*)d_in[1];
    const float* ln1_b  = (const float*)d_in[2];
    const float* qkv_w  = (const float*)d_in[3];
    const float* qkv_b  = (const float*)d_in[4];
    const float* proj_w = (const float*)d_in[5];
    const float* proj_b = (const float*)d_in[6];
    const float* rel_h  = (const float*)d_in[7];
    const float* rel_w  = (const float*)d_in[8];
    const float* ln2_g  = (const float*)d_in[9];
    const float* ln2_b  = (const float*)d_in[10];
    const float* fc1_w  = (const float*)d_in[11];
    const float* fc1_b  = (const float*)d_in[12];
    const float* fc2_w  = (const float*)d_in[13];
    const float* fc2_b  = (const float*)d_in[14];
    float* out = (float*)d_out;

    __half *p_xin, *p_qkv, *p_attn, *p_h2, *p_hid, *p_qkvb;
    __half *p_qkvT, *p_projT, *p_fc1T, *p_fc2T;
    float *p_xres;
    cudaGetSymbolAddress((void**)&p_xin,  g_xin_h);
    cudaGetSymbolAddress((void**)&p_qkv,  g_qkv_h);
    cudaGetSymbolAddress((void**)&p_attn, g_attn_h);
    cudaGetSymbolAddress((void**)&p_xres, g_xres);
    cudaGetSymbolAddress((void**)&p_h2,   g_h2_h);
    cudaGetSymbolAddress((void**)&p_hid,  g_hid_h);
    cudaGetSymbolAddress((void**)&p_qkvb, g_qkvb_h);
    cudaGetSymbolAddress((void**)&p_qkvT,  g_qkvwT);
    cudaGetSymbolAddress((void**)&p_projT, g_projwT);
    cudaGetSymbolAddress((void**)&p_fc1T,  g_fc1wT);
    cudaGetSymbolAddress((void**)&p_fc2T,  g_fc2wT);

    cudaFuncSetAttribute(attn_mma, cudaFuncAttributeMaxDynamicSharedMemorySize, ATT_SMEM);
    cudaFuncSetAttribute((const void*)gemm_h<false, false, true>,
                         cudaFuncAttributeMaxDynamicSharedMemorySize, GEMM_SMEM);
    cudaFuncSetAttribute((const void*)gemm_h<false, true, false>,
                         cudaFuncAttributeMaxDynamicSharedMemorySize, GEMM_SMEM);
    cudaFuncSetAttribute((const void*)gemm_h<true, false, true>,
                         cudaFuncAttributeMaxDynamicSharedMemorySize, GEMM_SMEM);

    // 0. all weight transposes + qkv bias to half (one launch)
    transpose_all<<<T_ALL, 256>>>(qkv_w, p_qkvT, proj_w, p_projT,
                                  fc1_w, p_fc1T, fc2_w, p_fc2T, qkv_b, p_qkvb);

    // 1. LN1 (token layout, half out)
    ln_kernel<<<GROWS, 256>>>(x, ln1_g, ln1_b, p_xin);

    // 2. QKV GEMM [8192,768]x[768,2304] -> half
    gemm_h<false, false, true><<<dim3(QKVN / 128, GROWS / 128), 256, GEMM_SMEM>>>(
        p_xin, p_qkvT, qkv_b, nullptr, p_qkv, GROWS, QKVN, DIM);

    // 3. mma attention (gathers windows; half out, token layout)
    attn_mma<<<NWIN * HEADS, 256, ATT_SMEM>>>(p_qkv, p_qkvb, rel_h, rel_w, p_attn);

    // 4. proj GEMM + residual -> fp32 xres
    gemm_h<false, true, false><<<dim3(DIM / 128, GROWS / 128), 256, GEMM_SMEM>>>(
        p_attn, p_projT, proj_b, x, p_xres, GROWS, DIM, DIM);

    // 5. LN2 (half out)
    ln_kernel<<<GROWS, 256>>>(p_xres, ln2_g, ln2_b, p_h2);

    // 6. fc1 + GELU (half out)
    gemm_h<true, false, true><<<dim3(MLPH / 128, GROWS / 128), 256, GEMM_SMEM>>>(
        p_h2, p_fc1T, fc1_b, nullptr, p_hid, GROWS, MLPH, DIM);

    // 7. fc2 + residual -> out (fp32)
    gemm_h<false, true, false><<<dim3(DIM / 128, GROWS / 128), 256, GEMM_SMEM>>>(
        p_hid, p_fc2T, fc2_b, p_xres, out, GROWS, DIM, MLPH);
}

// round 17
// speedup vs baseline: 1.7505x; 1.4146x over previous
#include <cuda_runtime.h>
#include <cuda_fp16.h>
#include <math.h>
#include <stdint.h>

#define DIM   768
#define HEADS 12
#define HD    64
#define WIN   14
#define NTOK  196
#define NWIN  50
#define GROWS 8192
#define MLPH  3072
#define QKVN  2304
#define SCALE 0.125f

// -------------------- scratch (device globals; no allocation) ----------------
__device__ __half g_xin_h [GROWS * DIM];
__device__ __half g_qkv_h [GROWS * QKVN];
__device__ __half g_attn_h[GROWS * DIM];
__device__ float  g_xres  [GROWS * DIM];
__device__ __half g_h2_h  [GROWS * DIM];
__device__ __half g_hid_h [GROWS * MLPH];
__device__ __half g_qkvwT [QKVN * DIM];
__device__ __half g_projwT[DIM * DIM];
__device__ __half g_fc1wT [MLPH * DIM];
__device__ __half g_fc2wT [DIM * MLPH];
__device__ __half g_qkvb_h[QKVN];

// -------------------- helpers ------------------------------------------------
__device__ __forceinline__ void cp16(void* dst, const void* src) {
    uint32_t d = (uint32_t)__cvta_generic_to_shared(dst);
    asm volatile("cp.async.cg.shared.global [%0], [%1], 16;\n" :: "r"(d), "l"(src));
}
#define CP_COMMIT()  asm volatile("cp.async.commit_group;\n")
#define CP_WAIT2()   asm volatile("cp.async.wait_group 2;\n")

__device__ __forceinline__ uint32_t packh2(float lo, float hi) {
    uint32_t r;
    asm("cvt.rn.f16x2.f32 %0, %1, %2;" : "=r"(r) : "f"(hi), "f"(lo));
    return r;
}

__device__ __forceinline__ void blockReduce2(float& s, float& ss) {
    #pragma unroll
    for (int o = 16; o; o >>= 1) {
        s  += __shfl_xor_sync(0xffffffffu, s,  o);
        ss += __shfl_xor_sync(0xffffffffu, ss, o);
    }
    __shared__ float ra[8], rb[8];
    int warp = threadIdx.x >> 5, lane = threadIdx.x & 31;
    if (lane == 0) { ra[warp] = s; rb[warp] = ss; }
    __syncthreads();
    if (threadIdx.x == 0) {
        float t1 = 0.f, t2 = 0.f;
        #pragma unroll
        for (int i = 0; i < 8; i++) { t1 += ra[i]; t2 += rb[i]; }
        ra[0] = t1; rb[0] = t2;
    }
    __syncthreads();
    s = ra[0]; ss = rb[0];
}

// -------------------- LayerNorm (token rows, half out) -----------------------
__global__ __launch_bounds__(256) void ln_kernel(
    const float* __restrict__ xin, const float* __restrict__ g,
    const float* __restrict__ b, __half* __restrict__ out)
{
    int t = blockIdx.x;
    const float* row = xin + (size_t)t * DIM;
    __half* orow = out + (size_t)t * DIM;
    int tid = threadIdx.x;
    float v0 = row[tid], v1 = row[tid + 256], v2 = row[tid + 512];
    float s = v0 + v1 + v2, ss = v0 * v0 + v1 * v1 + v2 * v2;
    blockReduce2(s, ss);
    float mean = s * (1.f / DIM);
    float var  = ss * (1.f / DIM) - mean * mean;
    float rstd = rsqrtf(var + 1e-6f);
    orow[tid]       = __float2half((v0 - mean) * rstd * g[tid]       + b[tid]);
    orow[tid + 256] = __float2half((v1 - mean) * rstd * g[tid + 256] + b[tid + 256]);
    orow[tid + 512] = __float2half((v2 - mean) * rstd * g[tid + 512] + b[tid + 512]);
}

// -------------------- all weight transposes + bias, one launch ---------------
#define T_QKV  1728
#define T_PROJ (T_QKV + 576)
#define T_FC1  (T_PROJ + 2304)
#define T_FC2  (T_FC1 + 2304)
#define T_ALL  (T_FC2 + 1)

__global__ __launch_bounds__(256) void transpose_all(
    const float* __restrict__ qkv_w,  __half* __restrict__ qkvT,
    const float* __restrict__ proj_w, __half* __restrict__ projT,
    const float* __restrict__ fc1_w,  __half* __restrict__ fc1T,
    const float* __restrict__ fc2_w,  __half* __restrict__ fc2T,
    const float* __restrict__ qkv_b,  __half* __restrict__ qkvb)
{
    int t = blockIdx.x;
    int lx = threadIdx.x & 31, ly = threadIdx.x >> 5;
    if (t >= T_FC2) {
        for (int i = threadIdx.x; i < QKVN; i += 256)
            qkvb[i] = __float2half(qkv_b[i]);
        return;
    }
    const float* in; __half* out; int R, C, nx;
    if (t < T_QKV)       { in = qkv_w;  out = qkvT;  R = DIM;  C = QKVN; nx = 72; }
    else if (t < T_PROJ) { t -= T_QKV;  in = proj_w; out = projT; R = DIM;  C = DIM;  nx = 24; }
    else if (t < T_FC1)  { t -= T_PROJ; in = fc1_w;  out = fc1T;  R = DIM;  C = MLPH; nx = 96; }
    else                 { t -= T_FC1;  in = fc2_w;  out = fc2T;  R = MLPH; C = DIM;  nx = 24; }
    int bx = (t % nx) << 5, by = (t / nx) << 5;

    __shared__ float tl[32][33];
    #pragma unroll
    for (int j = 0; j < 4; j++) {
        int r = by + ly + j * 8, c = bx + lx;
        tl[ly + j * 8][lx] = in[(size_t)r * C + c];
    }
    __syncthreads();
    #pragma unroll
    for (int j = 0; j < 4; j++) {
        int oc = by + lx, orr = bx + ly + j * 8;
        out[(size_t)orr * R + oc] = __float2half(tl[lx][ly + j * 8]);
    }
}

// -------------------- fp16 tensor-core GEMM (R12 config) ---------------------
#define RSTR 80
#define ASTG (128 * RSTR)
#define STG2 (2 * ASTG)
#define STAGES 4
#define GEMM_SMEM (STAGES * STG2)

template<bool GELU_ACT, bool RES, bool HALF_OUT>
__global__ __launch_bounds__(256, 2) void gemm_h(
    const __half* __restrict__ A, const __half* __restrict__ Bt,
    const float* __restrict__ bias, const float* __restrict__ Rs,
    void* __restrict__ Cv, int M, int Nn, int K)
{
    extern __shared__ char smc[];
    const int tid  = threadIdx.x;
    const int lane = tid & 31;
    const int warp = tid >> 5;
    const int wm = warp >> 2;
    const int wn = warp & 3;
    const int bm = blockIdx.y << 7;
    const int bn = blockIdx.x << 7;
    const int KT = K >> 5;

    const int lrow = tid >> 1;
    const int lch  = tid & 1;
    int gm = bm + lrow;
    int arow = gm < M ? gm : M - 1;
    const __half* srcA = A  + (size_t)arow * K + lch * 16;
    const __half* srcB = Bt + (size_t)(bn + lrow) * K + lch * 16;
    char* dA = smc + lrow * RSTR + lch * 32;
    char* dB = dA + ASTG;

    auto issue = [&](int kt, int s) {
        char* a = dA + s * STG2;
        char* b = dB + s * STG2;
        const __half* sa = srcA + kt * 32;
        const __half* sb = srcB + kt * 32;
        cp16(a, sa); cp16(a + 16, sa + 8);
        cp16(b, sb); cp16(b + 16, sb + 8);
    };

    uint32_t base0 = (uint32_t)__cvta_generic_to_shared(smc);
    const int l16 = lane & 15;
    const int lh  = lane >> 4;
    const uint32_t aoff = (uint32_t)((wm * 64 + l16) * RSTR + lh * 16);
    const uint32_t boff = (uint32_t)(ASTG + (wn * 32 + l16) * RSTR + lh * 16);

    float acc[4][4][4];
    #pragma unroll
    for (int i = 0; i < 4; i++)
        #pragma unroll
        for (int j = 0; j < 4; j++)
            #pragma unroll
            for (int c = 0; c < 4; c++) acc[i][j][c] = 0.f;

    issue(0, 0); CP_COMMIT();
    issue(1, 1); CP_COMMIT();
    issue(2, 2); CP_COMMIT();

    for (int kt = 0; kt < KT; kt++) {
        CP_WAIT2();
        __syncthreads();
        {
            int nk = kt + 3;
            if (nk < KT) issue(nk, nk & 3);
            CP_COMMIT();
        }

        uint32_t sb = base0 + (uint32_t)((kt & 3) * STG2);
        #pragma unroll
        for (int kh = 0; kh < 2; kh++) {
            uint32_t kb = (uint32_t)(kh * 32);
            uint32_t a[4][4], bw[2][4];
            #pragma unroll
            for (int mt = 0; mt < 4; mt++) {
                uint32_t ad = sb + aoff + (uint32_t)(mt * 16 * RSTR) + kb;
                asm volatile("ldmatrix.sync.aligned.m8n8.x4.shared.b16 {%0,%1,%2,%3}, [%4];"
                    : "=r"(a[mt][0]), "=r"(a[mt][1]), "=r"(a[mt][2]), "=r"(a[mt][3])
                    : "r"(ad));
            }
            #pragma unroll
            for (int g = 0; g < 2; g++) {
                uint32_t bd = sb + boff + (uint32_t)(g * 16 * RSTR) + kb;
                asm volatile("ldmatrix.sync.aligned.m8n8.x4.shared.b16 {%0,%1,%2,%3}, [%4];"
                    : "=r"(bw[g][0]), "=r"(bw[g][1]), "=r"(bw[g][2]), "=r"(bw[g][3])
                    : "r"(bd));
            }
            #pragma unroll
            for (int mt = 0; mt < 4; mt++)
                #pragma unroll
                for (int nt = 0; nt < 4; nt++) {
                    int g = nt >> 1, t = nt & 1;
                    asm volatile(
                        "mma.sync.aligned.m16n8k16.row.col.f32.f16.f16.f32 "
                        "{%0,%1,%2,%3}, {%4,%5,%6,%7}, {%8,%9}, {%0,%1,%2,%3};"
                        : "+f"(acc[mt][nt][0]), "+f"(acc[mt][nt][1]),
                          "+f"(acc[mt][nt][2]), "+f"(acc[mt][nt][3])
                        : "r"(a[mt][0]), "r"(a[mt][1]), "r"(a[mt][2]), "r"(a[mt][3]),
                          "r"(bw[g][t]), "r"(bw[g][t + 2]));
                }
        }
    }

    const int rbase = bm + wm * 64 + (lane >> 2);
    const int cbase = bn + wn * 32 + (lane & 3) * 2;
    float* Cf = (float*)Cv;
    __half* Ch = (__half*)Cv;
    #pragma unroll
    for (int nt = 0; nt < 4; nt++) {
        int col = cbase + nt * 8;
        float bs0 = bias[col], bs1 = bias[col + 1];
        #pragma unroll
        for (int mt = 0; mt < 4; mt++) {
            int r0 = rbase + mt * 16;
            int r1 = r0 + 8;
            float v00 = acc[mt][nt][0] + bs0;
            float v01 = acc[mt][nt][1] + bs1;
            float v10 = acc[mt][nt][2] + bs0;
            float v11 = acc[mt][nt][3] + bs1;
            if (GELU_ACT) {
                v00 = 0.5f * v00 * (1.f + erff(v00 * 0.70710678f));
                v01 = 0.5f * v01 * (1.f + erff(v01 * 0.70710678f));
                v10 = 0.5f * v10 * (1.f + erff(v10 * 0.70710678f));
                v11 = 0.5f * v11 * (1.f + erff(v11 * 0.70710678f));
            }
            if (r0 < M) {
                if (RES) {
                    const float* rr = Rs + (size_t)r0 * Nn + col;
                    v00 += rr[0]; v01 += rr[1];
                }
                if (HALF_OUT)
                    *(uint32_t*)(Ch + (size_t)r0 * Nn + col) = packh2(v00, v01);
                else
                    *(float2*)(Cf + (size_t)r0 * Nn + col) = make_float2(v00, v01);
            }
            if (r1 < M) {
                if (RES) {
                    const float* rr = Rs + (size_t)r1 * Nn + col;
                    v10 += rr[0]; v11 += rr[1];
                }
                if (HALF_OUT)
                    *(uint32_t*)(Ch + (size_t)r1 * Nn + col) = packh2(v10, v11);
                else
                    *(float2*)(Cf + (size_t)r1 * Nn + col) = make_float2(v10, v11);
            }
        }
    }
}

// -------------------- mma attention with one-hot rel-pos ---------------------
// Q'[i] = [q, rh(14), rw(14), pad]  (96 used of 120 halves, stride 240B)
// K'[j] = [k*SCALE, onehot(jh), onehot(jw), pad]
// S = Q' K'^T in one 6-kstep MMA loop; rel tables via 2 small MMAs + scatter.
#define QSTR 240
#define VSTR 144
#define ATT_Q   0
#define ATT_K   49920
#define ATT_V   99840
#define ATT_RH  129792
#define ATT_RW  134400
#define ATT_SMEM 139008

__global__ __launch_bounds__(256, 1) void attn_mma(
    const __half* __restrict__ qkv, const __half* __restrict__ qkvb,
    const float* __restrict__ relh, const float* __restrict__ relw,
    __half* __restrict__ outp)
{
    extern __shared__ char smb[];
    uint32_t sbase = (uint32_t)__cvta_generic_to_shared(smb);

    const int blk = blockIdx.x;
    const int w = blk / HEADS, h = blk % HEADS;
    const int img = w / 25, wy = (w % 25) / 5, wx = w % 5;
    const int tid = threadIdx.x, lane = tid & 31, warp = tid >> 5;

    const __half one = __float2half(1.f);
    const __half2 schalf = __half2half2(__float2half(SCALE));

    // ---- Q and K' fill: 208 rows x 15 chunks(16B) each ----
    for (int idx = tid; idx < 208 * 15 * 2; idx += 256) {
        int which = idx / (208 * 15);
        int rem = idx - which * (208 * 15);
        int j = rem / 15, c = rem - j * 15;
        uint4 val = make_uint4(0, 0, 0, 0);
        if (j < 196) {
            if (c < 8) {
                int ty = j / WIN, tx = j - ty * WIN;
                int y = wy * WIN + ty, xg = wx * WIN + tx;
                const uint4* src;
                if (y < 64 && xg < 64) {
                    int row = img * 4096 + y * 64 + xg;
                    src = (const uint4*)(qkv + (size_t)row * QKVN + which * DIM + h * HD + c * 8);
                } else {
                    src = (const uint4*)(qkvb + which * DIM + h * HD + c * 8);
                }
                val = *src;
                if (which) {
                    __half2* hv = (__half2*)&val;
                    hv[0] = __hmul2(hv[0], schalf); hv[1] = __hmul2(hv[1], schalf);
                    hv[2] = __hmul2(hv[2], schalf); hv[3] = __hmul2(hv[3], schalf);
                }
            } else if (which) {
                // one-hot region of K'
                int base = c * 8;
                int jh = j / WIN, jw = j - jh * WIN;
                __half* hv = (__half*)&val;
                int p1 = 64 + jh - base; if (p1 >= 0 && p1 < 8) hv[p1] = one;
                int p2 = 78 + jw - base; if (p2 >= 0 && p2 < 8) hv[p2] = one;
            }
        }
        *(uint4*)(smb + (which ? ATT_K : ATT_Q) + j * QSTR + c * 16) = val;
    }
    // ---- V fill: 208 rows x 9 chunks ----
    for (int idx = tid; idx < 208 * 9; idx += 256) {
        int j = idx / 9, c = idx - j * 9;
        uint4 val = make_uint4(0, 0, 0, 0);
        if (j < 196 && c < 8) {
            int ty = j / WIN, tx = j - ty * WIN;
            int y = wy * WIN + ty, xg = wx * WIN + tx;
            const uint4* src;
            if (y < 64 && xg < 64) {
                int row = img * 4096 + y * 64 + xg;
                src = (const uint4*)(qkv + (size_t)row * QKVN + 2 * DIM + h * HD + c * 8);
            } else {
                src = (const uint4*)(qkvb + 2 * DIM + h * HD + c * 8);
            }
            val = *src;
        }
        *(uint4*)(smb + ATT_V + j * VSTR + c * 16) = val;
    }
    // ---- rel tiles: 2 tables x 32 rows x 9 chunks (fp32 -> half) ----
    for (int idx = tid; idx < 2 * 32 * 9; idx += 256) {
        int sel = idx / (32 * 9);
        int rem = idx - sel * (32 * 9);
        int r = rem / 9, c = rem - r * 9;
        uint4 val = make_uint4(0, 0, 0, 0);
        if (r < 27 && c < 8) {
            const float4* s4 = (const float4*)((sel ? relw : relh) + r * HD + c * 8);
            float4 a = s4[0], b = s4[1];
            uint32_t* uv = (uint32_t*)&val;
            uv[0] = packh2(a.x, a.y); uv[1] = packh2(a.z, a.w);
            uv[2] = packh2(b.x, b.y); uv[3] = packh2(b.z, b.w);
        }
        *(uint4*)(smb + (sel ? ATT_RW : ATT_RH) + r * 144 + c * 16) = val;
    }
    __syncthreads();

    const int g = lane >> 2, qt = lane & 3;
    const int l8 = lane & 7;
    const int sel8 = (lane >> 3) & 1;

    for (int mt = warp; mt < 13; mt += 8) {
        const int i0 = mt * 16 + g, i1 = i0 + 8;
        const int ty0 = i0 / WIN, tx0 = i0 - ty0 * WIN;
        const int ty1 = i1 / WIN, tx1 = i1 - ty1 * WIN;

        // ---- Q fragments ks0..3 (q part only) ----
        uint32_t qf[6][4];
        #pragma unroll
        for (int ks = 0; ks < 4; ks++) {
            uint32_t ad = sbase + ATT_Q + (uint32_t)((mt * 16 + (lane & 15)) * QSTR
                        + ks * 32 + (lane >> 4) * 16);
            asm volatile("ldmatrix.sync.aligned.m8n8.x4.shared.b16 {%0,%1,%2,%3}, [%4];"
                : "=r"(qf[ks][0]), "=r"(qf[ks][1]), "=r"(qf[ks][2]), "=r"(qf[ks][3])
                : "r"(ad));
        }

        // ---- rel MMAs + scatter into Q' extension ----
        #pragma unroll
        for (int tab = 0; tab < 2; tab++) {
            const uint32_t rbase_s = sbase + (tab ? ATT_RW : ATT_RH);
            const int off = tab ? 78 : 64;
            const int tA0 = tab ? tx0 : ty0;
            const int tA1 = tab ? tx1 : ty1;
            #pragma unroll
            for (int nt = 0; nt < 4; nt++) {
                float r0 = 0.f, r1 = 0.f, r2 = 0.f, r3 = 0.f;
                #pragma unroll
                for (int ks = 0; ks < 4; ks++) {
                    uint32_t bd = rbase_s + (uint32_t)((nt * 8 + l8) * 144
                                + ks * 32 + sel8 * 16);
                    uint32_t b0, b1;
                    asm volatile("ldmatrix.sync.aligned.m8n8.x2.shared.b16 {%0,%1}, [%2];"
                        : "=r"(b0), "=r"(b1) : "r"(bd));
                    asm volatile(
                        "mma.sync.aligned.m16n8k16.row.col.f32.f16.f16.f32 "
                        "{%0,%1,%2,%3}, {%4,%5,%6,%7}, {%8,%9}, {%0,%1,%2,%3};"
                        : "+f"(r0), "+f"(r1), "+f"(r2), "+f"(r3)
                        : "r"(qf[ks][0]), "r"(qf[ks][1]), "r"(qf[ks][2]), "r"(qf[ks][3]),
                          "r"(b0), "r"(b1));
                }
                int c0 = nt * 8 + 2 * qt;
                int f;
                f = tA0 - c0 + 13;
                if (f >= 0 && f < 14)
                    *(__half*)(smb + ATT_Q + i0 * QSTR + (off + f) * 2) = __float2half(r0);
                f = tA0 - c0 + 12;
                if (f >= 0 && f < 14)
                    *(__half*)(smb + ATT_Q + i0 * QSTR + (off + f) * 2) = __float2half(r1);
                f = tA1 - c0 + 13;
                if (f >= 0 && f < 14)
                    *(__half*)(smb + ATT_Q + i1 * QSTR + (off + f) * 2) = __float2half(r2);
                f = tA1 - c0 + 12;
                if (f >= 0 && f < 14)
                    *(__half*)(smb + ATT_Q + i1 * QSTR + (off + f) * 2) = __float2half(r3);
            }
        }
        __syncwarp();

        // ---- Q fragments ks4,5 (rel extension) ----
        #pragma unroll
        for (int ks = 4; ks < 6; ks++) {
            uint32_t ad = sbase + ATT_Q + (uint32_t)((mt * 16 + (lane & 15)) * QSTR
                        + ks * 32 + (lane >> 4) * 16);
            asm volatile("ldmatrix.sync.aligned.m8n8.x4.shared.b16 {%0,%1,%2,%3}, [%4];"
                : "=r"(qf[ks][0]), "=r"(qf[ks][1]), "=r"(qf[ks][2]), "=r"(qf[ks][3])
                : "r"(ad));
        }

        // ---- S = Q' K'^T (6 k-steps, rel included) ----
        float S[26][4];
        #pragma unroll
        for (int nt = 0; nt < 26; nt++) {
            float s0 = 0.f, s1 = 0.f, s2 = 0.f, s3 = 0.f;
            #pragma unroll
            for (int ks = 0; ks < 6; ks++) {
                uint32_t kd = sbase + ATT_K + (uint32_t)((nt * 8 + l8) * QSTR
                            + ks * 32 + sel8 * 16);
                uint32_t b0, b1;
                asm volatile("ldmatrix.sync.aligned.m8n8.x2.shared.b16 {%0,%1}, [%2];"
                    : "=r"(b0), "=r"(b1) : "r"(kd));
                asm volatile(
                    "mma.sync.aligned.m16n8k16.row.col.f32.f16.f16.f32 "
                    "{%0,%1,%2,%3}, {%4,%5,%6,%7}, {%8,%9}, {%0,%1,%2,%3};"
                    : "+f"(s0), "+f"(s1), "+f"(s2), "+f"(s3)
                    : "r"(qf[ks][0]), "r"(qf[ks][1]), "r"(qf[ks][2]), "r"(qf[ks][3]),
                      "r"(b0), "r"(b1));
            }
            int j0 = nt * 8 + 2 * qt, j1 = j0 + 1;
            S[nt][0] = (j0 < 196) ? s0 : -1e30f;
            S[nt][1] = (j1 < 196) ? s1 : -1e30f;
            S[nt][2] = (j0 < 196) ? s2 : -1e30f;
            S[nt][3] = (j1 < 196) ? s3 : -1e30f;
        }

        // ---- softmax ----
        float mx0 = -1e30f, mx1 = -1e30f;
        #pragma unroll
        for (int nt = 0; nt < 26; nt++) {
            mx0 = fmaxf(mx0, fmaxf(S[nt][0], S[nt][1]));
            mx1 = fmaxf(mx1, fmaxf(S[nt][2], S[nt][3]));
        }
        mx0 = fmaxf(mx0, __shfl_xor_sync(0xffffffffu, mx0, 1));
        mx0 = fmaxf(mx0, __shfl_xor_sync(0xffffffffu, mx0, 2));
        mx1 = fmaxf(mx1, __shfl_xor_sync(0xffffffffu, mx1, 1));
        mx1 = fmaxf(mx1, __shfl_xor_sync(0xffffffffu, mx1, 2));
        float sum0 = 0.f, sum1 = 0.f;
        #pragma unroll
        for (int nt = 0; nt < 26; nt++) {
            S[nt][0] = __expf(S[nt][0] - mx0); sum0 += S[nt][0];
            S[nt][1] = __expf(S[nt][1] - mx0); sum0 += S[nt][1];
            S[nt][2] = __expf(S[nt][2] - mx1); sum1 += S[nt][2];
            S[nt][3] = __expf(S[nt][3] - mx1); sum1 += S[nt][3];
        }
        sum0 += __shfl_xor_sync(0xffffffffu, sum0, 1);
        sum0 += __shfl_xor_sync(0xffffffffu, sum0, 2);
        sum1 += __shfl_xor_sync(0xffffffffu, sum1, 1);
        sum1 += __shfl_xor_sync(0xffffffffu, sum1, 2);

        // ---- O = P V ----
        float O[8][4];
        #pragma unroll
        for (int nt = 0; nt < 8; nt++)
            #pragma unroll
            for (int c = 0; c < 4; c++) O[nt][c] = 0.f;

        #pragma unroll
        for (int kc = 0; kc < 13; kc++) {
            uint32_t p0 = packh2(S[2*kc][0],   S[2*kc][1]);
            uint32_t p1 = packh2(S[2*kc][2],   S[2*kc][3]);
            uint32_t p2 = packh2(S[2*kc+1][0], S[2*kc+1][1]);
            uint32_t p3 = packh2(S[2*kc+1][2], S[2*kc+1][3]);
            #pragma unroll
            for (int nt = 0; nt < 8; nt++) {
                uint32_t vd = sbase + ATT_V + (uint32_t)((kc * 16 + sel8 * 8 + l8) * VSTR
                            + nt * 16);
                uint32_t v0, v1;
                asm volatile("ldmatrix.sync.aligned.m8n8.x2.trans.shared.b16 {%0,%1}, [%2];"
                    : "=r"(v0), "=r"(v1) : "r"(vd));
                asm volatile(
                    "mma.sync.aligned.m16n8k16.row.col.f32.f16.f16.f32 "
                    "{%0,%1,%2,%3}, {%4,%5,%6,%7}, {%8,%9}, {%0,%1,%2,%3};"
                    : "+f"(O[nt][0]), "+f"(O[nt][1]), "+f"(O[nt][2]), "+f"(O[nt][3])
                    : "r"(p0), "r"(p1), "r"(p2), "r"(p3), "r"(v0), "r"(v1));
            }
        }

        // ---- write out (token layout; skip padded tokens) ----
        float inv0 = 1.f / sum0, inv1 = 1.f / sum1;
        if (i0 < 196) {
            int y = wy * WIN + ty0, xg = wx * WIN + tx0;
            if (y < 64 && xg < 64) {
                __half* orow = outp + ((size_t)(img * 4096 + y * 64 + xg)) * DIM + h * HD;
                #pragma unroll
                for (int nt = 0; nt < 8; nt++)
                    *(uint32_t*)(orow + nt * 8 + 2 * qt) =
                        packh2(O[nt][0] * inv0, O[nt][1] * inv0);
            }
        }
        if (i1 < 196) {
            int y = wy * WIN + ty1, xg = wx * WIN + tx1;
            if (y < 64 && xg < 64) {
                __half* orow = outp + ((size_t)(img * 4096 + y * 64 + xg)) * DIM + h * HD;
                #pragma unroll
                for (int nt = 0; nt < 8; nt++)
                    *(uint32_t*)(orow + nt * 8 + 2 * qt) =
                        packh2(O[nt][2] * inv1, O[nt][3] * inv1);
            }
        }
    }
}

// -------------------- launch -------------------------------------------------
extern "C" void kernel_launch(void* const* d_in, const int* in_sizes, int n_in,
                              void* d_out, int out_size)
{
    const float* x      = (const float*)d_in[0];
    const float* ln1_g  = (const float*)d_in[1];
    const float* ln1_b  = (const float*)d_in[2];
    const float* qkv_w  = (const float*)d_in[3];
    const float* qkv_b  = (const float*)d_in[4];
    const float* proj_w = (const float*)d_in[5];
    const float* proj_b = (const float*)d_in[6];
    const float* rel_h  = (const float*)d_in[7];
    const float* rel_w  = (const float*)d_in[8];
    const float* ln2_g  = (const float*)d_in[9];
    const float* ln2_b  = (const float*)d_in[10];
    const float* fc1_w  = (const float*)d_in[11];
    const float* fc1_b  = (const float*)d_in[12];
    const float* fc2_w  = (const float*)d_in[13];
    const float* fc2_b  = (const float*)d_in[14];
    float* out = (float*)d_out;

    __half *p_xin, *p_qkv, *p_attn, *p_h2, *p_hid, *p_qkvb;
    __half *p_qkvT, *p_projT, *p_fc1T, *p_fc2T;
    float *p_xres;
    cudaGetSymbolAddress((void**)&p_xin,  g_xin_h);
    cudaGetSymbolAddress((void**)&p_qkv,  g_qkv_h);
    cudaGetSymbolAddress((void**)&p_attn, g_attn_h);
    cudaGetSymbolAddress((void**)&p_xres, g_xres);
    cudaGetSymbolAddress((void**)&p_h2,   g_h2_h);
    cudaGetSymbolAddress((void**)&p_hid,  g_hid_h);
    cudaGetSymbolAddress((void**)&p_qkvb, g_qkvb_h);
    cudaGetSymbolAddress((void**)&p_qkvT,  g_qkvwT);
    cudaGetSymbolAddress((void**)&p_projT, g_projwT);
    cudaGetSymbolAddress((void**)&p_fc1T,  g_fc1wT);
    cudaGetSymbolAddress((void**)&p_fc2T,  g_fc2wT);

    cudaFuncSetAttribute(attn_mma, cudaFuncAttributeMaxDynamicSharedMemorySize, ATT_SMEM);
    cudaFuncSetAttribute((const void*)gemm_h<false, false, true>,
                         cudaFuncAttributeMaxDynamicSharedMemorySize, GEMM_SMEM);
    cudaFuncSetAttribute((const void*)gemm_h<false, true, false>,
                         cudaFuncAttributeMaxDynamicSharedMemorySize, GEMM_SMEM);
    cudaFuncSetAttribute((const void*)gemm_h<true, false, true>,
                         cudaFuncAttributeMaxDynamicSharedMemorySize, GEMM_SMEM);

    // 0. all weight transposes + qkv bias to half (one launch)
    transpose_all<<<T_ALL, 256>>>(qkv_w, p_qkvT, proj_w, p_projT,
                                  fc1_w, p_fc1T, fc2_w, p_fc2T, qkv_b, p_qkvb);

    // 1. LN1 (token layout, half out)
    ln_kernel<<<GROWS, 256>>>(x, ln1_g, ln1_b, p_xin);

    // 2. QKV GEMM [8192,768]x[768,2304] -> half
    gemm_h<false, false, true><<<dim3(QKVN / 128, GROWS / 128), 256, GEMM_SMEM>>>(
        p_xin, p_qkvT, qkv_b, nullptr, p_qkv, GROWS, QKVN, DIM);

    // 3. mma attention with one-hot rel-pos (half out, token layout)
    attn_mma<<<NWIN * HEADS, 256, ATT_SMEM>>>(p_qkv, p_qkvb, rel_h, rel_w, p_attn);

    // 4. proj GEMM + residual -> fp32 xres
    gemm_h<false, true, false><<<dim3(DIM / 128, GROWS / 128), 256, GEMM_SMEM>>>(
        p_attn, p_projT, proj_b, x, p_xres, GROWS, DIM, DIM);

    // 5. LN2 (half out)
    ln_kernel<<<GROWS, 256>>>(p_xres, ln2_g, ln2_b, p_h2);

    // 6. fc1 + GELU (half out)
    gemm_h<true, false, true><<<dim3(MLPH / 128, GROWS / 128), 256, GEMM_SMEM>>>(
        p_h2, p_fc1T, fc1_b, nullptr, p_hid, GROWS, MLPH, DIM);

    // 7. fc2 + residual -> out (fp32)
    gemm_h<false, true, false><<<dim3(DIM / 128, GROWS / 128), 256, GEMM_SMEM>>>(
        p_hid, p_fc2T, fc2_b, p_xres, out, GROWS, DIM, MLPH);
}